// round 7
// baseline (speedup 1.0000x reference)
#include <cuda_runtime.h>
#include <cuda_bf16.h>

#define IMG_H 512
#define IMG_W 512
#define FXc 500.0f
#define FYc 500.0f
#define CXc 256.0f
#define CYc 256.0f
#define NG  256
#define NCHUNK 4

// K = 0.5*log2(e) folded as sqrt(K) into mu*s params.
#define SQRT_K 0.8493218002880191f
// valid gate: num' > 0.1*sqrt(K)*den
#define VALID_C 0.08493218002880191f

typedef unsigned long long u64;

// Compacted, padded, packed (duplicated-pair) sorted gaussian params.
// Per gaussian: 5 x ulonglong2:
//  e0 = { {ms0',ms0'}, {ms1',ms1'} }
//  e1 = { {ms2',ms2'}, {s0,s0} }
//  e2 = { {s1,s1},     {s2,s2} }
//  e3 = { {la,la},     {c0,c0} }   la = log2( sigmoid(op)*exp(-0.5*m2) )
//  e4 = { {c1,c1},     {c2,c2} }
__device__ ulonglong2 g_packed[(NG + 32) * 5];
__device__ int d_L;   // per-chunk length (multiple of 8), 4*L >= nvis

// Per-chunk compositing state {r,g,b,T} per pixel.
__device__ float4 g_scratch[NCHUNK * IMG_H * IMG_W];

__global__ void prep_kernel(const float* __restrict__ pos,
                            const float* __restrict__ ls,
                            const float* __restrict__ rop,
                            const float* __restrict__ col) {
    const int i = threadIdx.x;
    __shared__ float zs[NG];
    __shared__ int visr[NG];
    const float z = pos[i * 3 + 2];
    zs[i] = z;
    __syncthreads();

    // Stable rank = jnp.argsort position (ascending, stable ties).
    int rank = 0;
#pragma unroll 16
    for (int j = 0; j < NG; j++) {
        const float zj = zs[j];
        rank += (zj < z) || (zj == z && j < i);
    }

    const float mu0 = pos[i * 3 + 0];
    const float mu1 = pos[i * 3 + 1];
    const float mu2 = z;

    const float e0 = expf(ls[i * 3 + 0]);
    const float e1 = expf(ls[i * 3 + 1]);
    const float e2 = expf(ls[i * 3 + 2]);
    const float s0 = 1.0f / (e0 * e0);
    const float s1 = 1.0f / (e1 * e1);
    const float s2 = 1.0f / (e2 * e2);

    const float ms0 = mu0 * s0;
    const float ms1 = mu1 * s1;
    const float ms2 = mu2 * s2;
    const float m2  = mu0 * ms0 + mu1 * ms1 + mu2 * ms2;

    const float a0  = 1.0f / (1.0f + expf(-rop[i]));
    const float la  = log2f(a0) - 0.72134752044448170367f * m2;
    const float c0 = 1.0f / (1.0f + expf(-col[i * 3 + 0]));
    const float c1 = 1.0f / (1.0f + expf(-col[i * 3 + 1]));
    const float c2 = 1.0f / (1.0f + expf(-col[i * 3 + 2]));

    // EXACT frustum cull (see R5): if num_max <= VALID_C*s2*0.81, alpha==0 everywhere.
    const float R = 0.511f;
    const float num_max = ms2 + R * (fabsf(ms0) + fabsf(ms1));
    const int vis = (num_max > VALID_C * s2 * 0.81f) ? 1 : 0;

    visr[rank] = vis;
    __syncthreads();

    int cidx = 0, total = 0;
#pragma unroll 16
    for (int j = 0; j < NG; j++) {
        const int v = visr[j];
        cidx  += (j < rank) ? v : 0;
        total += v;
    }

    if (vis) {
        float* gp = (float*)&g_packed[cidx * 5];
        gp[0]  = ms0 * SQRT_K; gp[1]  = gp[0];
        gp[2]  = ms1 * SQRT_K; gp[3]  = gp[2];
        gp[4]  = ms2 * SQRT_K; gp[5]  = gp[4];
        gp[6]  = s0;           gp[7]  = s0;
        gp[8]  = s1;           gp[9]  = s1;
        gp[10] = s2;           gp[11] = s2;
        gp[12] = la;           gp[13] = la;
        gp[14] = c0;           gp[15] = c0;
        gp[16] = c1;           gp[17] = c1;
        gp[18] = c2;           gp[19] = c2;
    }

    // Per-chunk length L: multiple of 8, NCHUNK*L >= total.
    const int L = ((total + NCHUNK * 8 - 1) / (NCHUNK * 8)) * 8;
    const int padn = NCHUNK * L - total;
    // Exact no-op pad entries: num=0 fails gate -> alpha=0.
    if (i < padn) {
        float* gp = (float*)&g_packed[(total + i) * 5];
#pragma unroll
        for (int k = 0; k < 20; k++) gp[k] = 0.0f;
        gp[6] = gp[7] = gp[8] = gp[9] = gp[10] = gp[11] = 1.0f;  // s=1 -> den>0
        gp[12] = gp[13] = -100.0f;
    }
    if (i == 0) d_L = L;
}

__device__ __forceinline__ float fast_ex2(float x) {
    float r;
    asm("ex2.approx.ftz.f32 %0, %1;" : "=f"(r) : "f"(x));
    return r;
}
__device__ __forceinline__ float fast_rcp(float x) {
    float r;
    asm("rcp.approx.ftz.f32 %0, %1;" : "=f"(r) : "f"(x));
    return r;
}
__device__ __forceinline__ u64 fma2(u64 a, u64 b, u64 c) {
    u64 d; asm("fma.rn.f32x2 %0, %1, %2, %3;" : "=l"(d) : "l"(a), "l"(b), "l"(c)); return d;
}
__device__ __forceinline__ u64 mul2(u64 a, u64 b) {
    u64 d; asm("mul.rn.f32x2 %0, %1, %2;" : "=l"(d) : "l"(a), "l"(b)); return d;
}
__device__ __forceinline__ u64 pk(float lo, float hi) {
    u64 d; asm("mov.b64 %0, {%1, %2};" : "=l"(d) : "f"(lo), "f"(hi)); return d;
}
__device__ __forceinline__ void upk(float& lo, float& hi, u64 a) {
    asm("mov.b64 {%0, %1}, %2;" : "=f"(lo), "=f"(hi) : "l"(a));
}

// One block = (half image row) x (z-chunk). 128 threads, 2 px/thread.
__global__ __launch_bounds__(128) void render_kernel() {
    __shared__ ulonglong2 sg[64 * 5];   // L <= 64
    const int t = threadIdx.x;
    const int L = d_L;
    const int chunk = blockIdx.x >> 10;
    const int pb    = blockIdx.x & 1023;

    for (int k = t; k < L * 5; k += 128) sg[k] = g_packed[chunk * L * 5 + k];

    const int y  = pb >> 1;
    const int x0 = ((pb & 1) << 8) + 2 * t;
    const int x1 = x0 + 1;

    const float dyr = (y + 0.5f - CYc) * (1.0f / FYc);
    float ax0 = (x0 + 0.5f - CXc) * (1.0f / FXc);
    float ax1 = (x1 + 0.5f - CXc) * (1.0f / FXc);
    const float rn0 = rsqrtf(fmaf(ax0, ax0, fmaf(dyr, dyr, 1.0f)));
    const float rn1 = rsqrtf(fmaf(ax1, ax1, fmaf(dyr, dyr, 1.0f)));

    const u64 dx2  = pk(ax0 * rn0, ax1 * rn1);
    const u64 dy2  = pk(dyr * rn0, dyr * rn1);
    const u64 dz2  = pk(rn0, rn1);
    const u64 dxx2 = mul2(dx2, dx2), dyy2 = mul2(dy2, dy2), dzz2 = mul2(dz2, dz2);
    const u64 NEG1 = pk(-1.0f, -1.0f);
    const u64 NVC2 = pk(-VALID_C, -VALID_C);

    __syncthreads();

    u64 T2  = pk(1.0f, 1.0f);
    u64 cr2 = pk(0.0f, 0.0f), cg2 = cr2, cb2 = cr2;

    for (int ib = 0; ib < L; ib += 8) {
        // Warp-level early termination (remaining local contribution < 1e-7).
        float t0, t1;
        upk(t0, t1, T2);
        if (__all_sync(0xffffffffu, fmaxf(t0, t1) < 1e-7f)) break;

#pragma unroll
        for (int j = 0; j < 8; j++) {
            const int i = ib + j;
            const ulonglong2 e0 = sg[i * 5 + 0];
            const ulonglong2 e1 = sg[i * 5 + 1];
            const ulonglong2 e2 = sg[i * 5 + 2];
            const ulonglong2 e3 = sg[i * 5 + 3];
            const ulonglong2 e4 = sg[i * 5 + 4];

            const u64 num2 = fma2(e0.x, dx2, fma2(e0.y, dy2, mul2(e1.x, dz2)));
            const u64 den2 = fma2(e1.y, dxx2, fma2(e2.x, dyy2, mul2(e2.y, dzz2)));
            const u64 nn2  = mul2(num2, num2);
            const u64 gg2  = fma2(den2, NVC2, num2);   // >0 <=> tau gate passes

            float g0, g1, d0, d1, q0, q1, la, la_;
            upk(g0, g1, gg2);
            upk(d0, d1, den2);
            upk(q0, q1, nn2);
            upk(la, la_, e3.x);

            // Batched reciprocal: one MUFU rcp serves both pixels.
            const float r  = fast_rcp(d0 * d1);
            const float i0 = r * d1;
            const float i1 = r * d0;

            const float arg0 = (g0 > 0.0f) ? fmaf(q0, i0, la) : -1e30f;
            const float arg1 = (g1 > 0.0f) ? fmaf(q1, i1, la) : -1e30f;
            const float al0 = fast_ex2(arg0);
            const float al1 = fast_ex2(arg1);

            const u64 w2 = mul2(T2, pk(al0, al1));
            cr2 = fma2(w2, e3.y, cr2);
            cg2 = fma2(w2, e4.x, cg2);
            cb2 = fma2(w2, e4.y, cb2);
            T2  = fma2(w2, NEG1, T2);
        }
    }

    float r0, r1, g0, g1, b0, b1, t0, t1;
    upk(r0, r1, cr2);
    upk(g0, g1, cg2);
    upk(b0, b1, cb2);
    upk(t0, t1, T2);

    float4* sc = &g_scratch[chunk * (IMG_H * IMG_W) + y * IMG_W + x0];
    sc[0] = make_float4(r0, g0, b0, t0);
    sc[1] = make_float4(r1, g1, b1, t1);
}

// Fold 4 chunk states: out = i0 + T0*(i1 + T1*(i2 + T2*(i3 + T3))).
__global__ __launch_bounds__(128) void merge_kernel(float* __restrict__ out) {
    const int base = (blockIdx.x * 128 + threadIdx.x) * 2;   // pixel index, 2 px/thread

#pragma unroll 2
    for (int p = 0; p < 2; p++) {
        const int px = base + p;
        const float4 a0 = g_scratch[0 * (IMG_H * IMG_W) + px];
        const float4 a1 = g_scratch[1 * (IMG_H * IMG_W) + px];
        const float4 a2 = g_scratch[2 * (IMG_H * IMG_W) + px];
        const float4 a3 = g_scratch[3 * (IMG_H * IMG_W) + px];

        float r = a3.x + a3.w, g = a3.y + a3.w, b = a3.z + a3.w;
        r = fmaf(a2.w, r, a2.x); g = fmaf(a2.w, g, a2.y); b = fmaf(a2.w, b, a2.z);
        r = fmaf(a1.w, r, a1.x); g = fmaf(a1.w, g, a1.y); b = fmaf(a1.w, b, a1.z);
        r = fmaf(a0.w, r, a0.x); g = fmaf(a0.w, g, a0.y); b = fmaf(a0.w, b, a0.z);

        out[px * 3 + 0] = r;
        out[px * 3 + 1] = g;
        out[px * 3 + 2] = b;
    }
}

extern "C" void kernel_launch(void* const* d_in, const int* in_sizes, int n_in,
                              void* d_out, int out_size) {
    const float* pos = (const float*)d_in[0];
    const float* ls  = (const float*)d_in[1];
    const float* rop = (const float*)d_in[2];
    const float* col = (const float*)d_in[3];
    float* out = (float*)d_out;

    prep_kernel<<<1, NG>>>(pos, ls, rop, col);
    render_kernel<<<1024 * NCHUNK, 128>>>();
    merge_kernel<<<(IMG_H * IMG_W) / 256, 128>>>(out);
}

// round 8
// speedup vs baseline: 1.0270x; 1.0270x over previous
#include <cuda_runtime.h>
#include <cuda_bf16.h>

#define IMG_H 512
#define IMG_W 512
#define FXc 500.0f
#define FYc 500.0f
#define CXc 256.0f
#define CYc 256.0f
#define NG  256
#define NCHUNK 4

// K = 0.5*log2(e) folded as sqrt(K) into mu*s params.
#define SQRT_K 0.8493218002880191f
// valid gate: num' > 0.1*sqrt(K)*den
#define VALID_C 0.08493218002880191f

typedef unsigned long long u64;

// Compacted, padded, packed (duplicated-pair) sorted gaussian params.
// Per gaussian: 5 x ulonglong2:
//  e0 = { {ms0',ms0'}, {ms1',ms1'} }
//  e1 = { {ms2',ms2'}, {s0,s0} }
//  e2 = { {s1,s1},     {s2,s2} }
//  e3 = { {la,la},     {c0,c0} }   la = log2( sigmoid(op)*exp(-0.5*m2) )
//  e4 = { {c1,c1},     {c2,c2} }
__device__ ulonglong2 g_packed[(NG + 32) * 5];
__device__ int d_L;   // per-chunk length (multiple of 8), NCHUNK*L >= nvis

// Per-chunk compositing state {r,g,b,T} per pixel.
__device__ float4 g_scratch[NCHUNK * IMG_H * IMG_W];

__global__ void prep_kernel(const float* __restrict__ pos,
                            const float* __restrict__ ls,
                            const float* __restrict__ rop,
                            const float* __restrict__ col) {
    const int i = threadIdx.x;
    __shared__ float sp[NG * 3], sl[NG * 3], so[NG], sc[NG * 3];
    __shared__ float zs[NG];
    __shared__ int visr[NG];

    // Coalesced parallel staging of all inputs (one latency round).
    for (int k = i; k < NG * 3; k += NG) {
        sp[k] = pos[k];
        sl[k] = ls[k];
        sc[k] = col[k];
    }
    so[i] = rop[i];
    __syncthreads();

    const float z = sp[i * 3 + 2];
    zs[i] = z;
    __syncthreads();

    // Stable rank = jnp.argsort position (ascending, stable ties).
    int rank = 0;
#pragma unroll 16
    for (int j = 0; j < NG; j++) {
        const float zj = zs[j];
        rank += (zj < z) || (zj == z && j < i);
    }

    const float mu0 = sp[i * 3 + 0];
    const float mu1 = sp[i * 3 + 1];
    const float mu2 = z;

    const float e0 = expf(sl[i * 3 + 0]);
    const float e1 = expf(sl[i * 3 + 1]);
    const float e2 = expf(sl[i * 3 + 2]);
    const float s0 = 1.0f / (e0 * e0);
    const float s1 = 1.0f / (e1 * e1);
    const float s2 = 1.0f / (e2 * e2);

    const float ms0 = mu0 * s0;
    const float ms1 = mu1 * s1;
    const float ms2 = mu2 * s2;
    const float m2  = mu0 * ms0 + mu1 * ms1 + mu2 * ms2;

    const float a0  = 1.0f / (1.0f + expf(-so[i]));
    const float la  = log2f(a0) - 0.72134752044448170367f * m2;
    const float c0 = 1.0f / (1.0f + expf(-sc[i * 3 + 0]));
    const float c1 = 1.0f / (1.0f + expf(-sc[i * 3 + 1]));
    const float c2 = 1.0f / (1.0f + expf(-sc[i * 3 + 2]));

    // EXACT frustum cull (R5): if num_max <= VALID_C*s2*0.81, alpha==0 everywhere.
    const float R = 0.511f;
    const float num_max = ms2 + R * (fabsf(ms0) + fabsf(ms1));
    const int vis = (num_max > VALID_C * s2 * 0.81f) ? 1 : 0;

    visr[rank] = vis;
    __syncthreads();

    int cidx = 0, total = 0;
#pragma unroll 16
    for (int j = 0; j < NG; j++) {
        const int v = visr[j];
        cidx  += (j < rank) ? v : 0;
        total += v;
    }

    if (vis) {
        float* gp = (float*)&g_packed[cidx * 5];
        gp[0]  = ms0 * SQRT_K; gp[1]  = gp[0];
        gp[2]  = ms1 * SQRT_K; gp[3]  = gp[2];
        gp[4]  = ms2 * SQRT_K; gp[5]  = gp[4];
        gp[6]  = s0;           gp[7]  = s0;
        gp[8]  = s1;           gp[9]  = s1;
        gp[10] = s2;           gp[11] = s2;
        gp[12] = la;           gp[13] = la;
        gp[14] = c0;           gp[15] = c0;
        gp[16] = c1;           gp[17] = c1;
        gp[18] = c2;           gp[19] = c2;
    }

    // Per-chunk length L: multiple of 8, NCHUNK*L >= total.
    const int L = ((total + NCHUNK * 8 - 1) / (NCHUNK * 8)) * 8;
    const int padn = NCHUNK * L - total;
    // Exact no-op pad entries: num=0 fails gate -> alpha=0.
    if (i < padn) {
        float* gp = (float*)&g_packed[(total + i) * 5];
#pragma unroll
        for (int k = 0; k < 20; k++) gp[k] = 0.0f;
        gp[6] = gp[7] = gp[8] = gp[9] = gp[10] = gp[11] = 1.0f;  // s=1 -> den>0
        gp[12] = gp[13] = -100.0f;
    }
    if (i == 0) d_L = L;
}

__device__ __forceinline__ float fast_ex2(float x) {
    float r;
    asm("ex2.approx.ftz.f32 %0, %1;" : "=f"(r) : "f"(x));
    return r;
}
__device__ __forceinline__ float fast_rcp(float x) {
    float r;
    asm("rcp.approx.ftz.f32 %0, %1;" : "=f"(r) : "f"(x));
    return r;
}
__device__ __forceinline__ u64 fma2(u64 a, u64 b, u64 c) {
    u64 d; asm("fma.rn.f32x2 %0, %1, %2, %3;" : "=l"(d) : "l"(a), "l"(b), "l"(c)); return d;
}
__device__ __forceinline__ u64 mul2(u64 a, u64 b) {
    u64 d; asm("mul.rn.f32x2 %0, %1, %2;" : "=l"(d) : "l"(a), "l"(b)); return d;
}
__device__ __forceinline__ u64 pk(float lo, float hi) {
    u64 d; asm("mov.b64 %0, {%1, %2};" : "=l"(d) : "f"(lo), "f"(hi)); return d;
}
__device__ __forceinline__ void upk(float& lo, float& hi, u64 a) {
    asm("mov.b64 {%0, %1}, %2;" : "=f"(lo), "=f"(hi) : "l"(a));
}

// One block = (image row) x (z-chunk). 128 threads, 4 px/thread (two packed chains).
__global__ __launch_bounds__(128) void render_kernel() {
    __shared__ ulonglong2 sg[64 * 5];   // L <= 64
    const int t = threadIdx.x;
    const int L = d_L;
    const int chunk = blockIdx.x >> 9;
    const int y     = blockIdx.x & 511;

    for (int k = t; k < L * 5; k += 128) sg[k] = g_packed[chunk * L * 5 + k];

    const int xb = 4 * t;

    const float dyr = (y + 0.5f - CYc) * (1.0f / FYc);
    float dxs[4], dys[4], dzs[4];
#pragma unroll
    for (int p = 0; p < 4; p++) {
        const float ax = (xb + p + 0.5f - CXc) * (1.0f / FXc);
        const float rn = rsqrtf(fmaf(ax, ax, fmaf(dyr, dyr, 1.0f)));
        dxs[p] = ax * rn; dys[p] = dyr * rn; dzs[p] = rn;
    }

    const u64 dxA = pk(dxs[0], dxs[1]), dxB = pk(dxs[2], dxs[3]);
    const u64 dyA = pk(dys[0], dys[1]), dyB = pk(dys[2], dys[3]);
    const u64 dzA = pk(dzs[0], dzs[1]), dzB = pk(dzs[2], dzs[3]);
    const u64 dxxA = mul2(dxA, dxA), dxxB = mul2(dxB, dxB);
    const u64 dyyA = mul2(dyA, dyA), dyyB = mul2(dyB, dyB);
    const u64 dzzA = mul2(dzA, dzA), dzzB = mul2(dzB, dzB);
    const u64 NEG1 = pk(-1.0f, -1.0f);
    const u64 NVC2 = pk(-VALID_C, -VALID_C);

    __syncthreads();

    u64 TA = pk(1.0f, 1.0f), TB = TA;
    u64 crA = pk(0.0f, 0.0f), cgA = crA, cbA = crA;
    u64 crB = crA, cgB = crA, cbB = crA;

    for (int ib = 0; ib < L; ib += 8) {
        float tA0, tA1, tB0, tB1;
        upk(tA0, tA1, TA);
        upk(tB0, tB1, TB);
        const float tmax = fmaxf(fmaxf(tA0, tA1), fmaxf(tB0, tB1));
        if (__all_sync(0xffffffffu, tmax < 1e-7f)) break;

#pragma unroll
        for (int j = 0; j < 8; j++) {
            const int i = ib + j;
            const ulonglong2 e0 = sg[i * 5 + 0];
            const ulonglong2 e1 = sg[i * 5 + 1];
            const ulonglong2 e2 = sg[i * 5 + 2];
            const ulonglong2 e3 = sg[i * 5 + 3];
            const ulonglong2 e4 = sg[i * 5 + 4];

            const u64 numA = fma2(e0.x, dxA, fma2(e0.y, dyA, mul2(e1.x, dzA)));
            const u64 numB = fma2(e0.x, dxB, fma2(e0.y, dyB, mul2(e1.x, dzB)));
            const u64 denA = fma2(e1.y, dxxA, fma2(e2.x, dyyA, mul2(e2.y, dzzA)));
            const u64 denB = fma2(e1.y, dxxB, fma2(e2.x, dyyB, mul2(e2.y, dzzB)));
            const u64 nnA = mul2(numA, numA);
            const u64 nnB = mul2(numB, numB);
            const u64 ggA = fma2(denA, NVC2, numA);   // >0 <=> tau gate passes
            const u64 ggB = fma2(denB, NVC2, numB);

            float gA0, gA1, gB0, gB1, dA0, dA1, dB0, dB1;
            float qA0, qA1, qB0, qB1, la, la_;
            upk(gA0, gA1, ggA); upk(gB0, gB1, ggB);
            upk(dA0, dA1, denA); upk(dB0, dB1, denB);
            upk(qA0, qA1, nnA);  upk(qB0, qB1, nnB);
            upk(la, la_, e3.x);

            // Batched reciprocal: one MUFU rcp per pixel pair.
            const float rA = fast_rcp(dA0 * dA1);
            const float rB = fast_rcp(dB0 * dB1);
            const float iA0 = rA * dA1, iA1 = rA * dA0;
            const float iB0 = rB * dB1, iB1 = rB * dB0;

            const float argA0 = (gA0 > 0.0f) ? fmaf(qA0, iA0, la) : -1e30f;
            const float argA1 = (gA1 > 0.0f) ? fmaf(qA1, iA1, la) : -1e30f;
            const float argB0 = (gB0 > 0.0f) ? fmaf(qB0, iB0, la) : -1e30f;
            const float argB1 = (gB1 > 0.0f) ? fmaf(qB1, iB1, la) : -1e30f;

            const u64 alA = pk(fast_ex2(argA0), fast_ex2(argA1));
            const u64 alB = pk(fast_ex2(argB0), fast_ex2(argB1));

            const u64 wA = mul2(TA, alA);
            const u64 wB = mul2(TB, alB);
            crA = fma2(wA, e3.y, crA);  crB = fma2(wB, e3.y, crB);
            cgA = fma2(wA, e4.x, cgA);  cgB = fma2(wB, e4.x, cgB);
            cbA = fma2(wA, e4.y, cbA);  cbB = fma2(wB, e4.y, cbB);
            TA  = fma2(wA, NEG1, TA);   TB  = fma2(wB, NEG1, TB);
        }
    }

    float rA0, rA1, gA0, gA1, bA0, bA1, tA0, tA1;
    float rB0, rB1, gB0, gB1, bB0, bB1, tB0, tB1;
    upk(rA0, rA1, crA); upk(gA0, gA1, cgA); upk(bA0, bA1, cbA); upk(tA0, tA1, TA);
    upk(rB0, rB1, crB); upk(gB0, gB1, cgB); upk(bB0, bB1, cbB); upk(tB0, tB1, TB);

    float4* sc = &g_scratch[chunk * (IMG_H * IMG_W) + y * IMG_W + xb];
    sc[0] = make_float4(rA0, gA0, bA0, tA0);
    sc[1] = make_float4(rA1, gA1, bA1, tA1);
    sc[2] = make_float4(rB0, gB0, bB0, tB0);
    sc[3] = make_float4(rB1, gB1, bB1, tB1);
}

// Fold 4 chunk states: out = i0 + T0*(i1 + T1*(i2 + T2*(i3 + T3))).
__global__ __launch_bounds__(128) void merge_kernel(float* __restrict__ out) {
    const int base = (blockIdx.x * 128 + threadIdx.x) * 2;

#pragma unroll 2
    for (int p = 0; p < 2; p++) {
        const int px = base + p;
        const float4 a0 = g_scratch[0 * (IMG_H * IMG_W) + px];
        const float4 a1 = g_scratch[1 * (IMG_H * IMG_W) + px];
        const float4 a2 = g_scratch[2 * (IMG_H * IMG_W) + px];
        const float4 a3 = g_scratch[3 * (IMG_H * IMG_W) + px];

        float r = a3.x + a3.w, g = a3.y + a3.w, b = a3.z + a3.w;
        r = fmaf(a2.w, r, a2.x); g = fmaf(a2.w, g, a2.y); b = fmaf(a2.w, b, a2.z);
        r = fmaf(a1.w, r, a1.x); g = fmaf(a1.w, g, a1.y); b = fmaf(a1.w, b, a1.z);
        r = fmaf(a0.w, r, a0.x); g = fmaf(a0.w, g, a0.y); b = fmaf(a0.w, b, a0.z);

        out[px * 3 + 0] = r;
        out[px * 3 + 1] = g;
        out[px * 3 + 2] = b;
    }
}

extern "C" void kernel_launch(void* const* d_in, const int* in_sizes, int n_in,
                              void* d_out, int out_size) {
    const float* pos = (const float*)d_in[0];
    const float* ls  = (const float*)d_in[1];
    const float* rop = (const float*)d_in[2];
    const float* col = (const float*)d_in[3];
    float* out = (float*)d_out;

    prep_kernel<<<1, NG>>>(pos, ls, rop, col);
    render_kernel<<<IMG_H * NCHUNK, 128>>>();
    merge_kernel<<<(IMG_H * IMG_W) / 256, 128>>>(out);
}